// round 5
// baseline (speedup 1.0000x reference)
#include <cuda_runtime.h>
#include <math.h>

#define N_NODES 10000
#define N_EDGES 320000
#define E2      (N_EDGES + N_NODES)   // + self loops
#define IN_CH   512
#define D1      512                   // HEADS * HID
#define HEADS   4
#define HID     128
#define NEG_SLOPE 0.2f

// ---------------- scratch (no allocations allowed) ----------------
__device__ __align__(16) float g_h1  [N_NODES * D1];   // x @ W1
__device__ __align__(16) float g_act1[N_NODES * D1];   // elu(agg1 + b1)
__device__ float g_asrc1[N_NODES * HEADS];
__device__ float g_adst1[N_NODES * HEADS];
__device__ __align__(16) float g_h2[N_NODES * 2];
__device__ float g_asrc2[N_NODES];
__device__ float g_adst2[N_NODES];
__device__ int g_deg[N_NODES];
__device__ int g_row[N_NODES + 1];
__device__ int g_cur[N_NODES];
__device__ int g_csr[E2];

// ---------------- helpers ----------------
__device__ __forceinline__ float lrelu(float e) { return e > 0.f ? e : NEG_SLOPE * e; }

// ---------------- kernel: zero degree histogram ----------------
__global__ void k_zero() {
    int i = blockIdx.x * blockDim.x + threadIdx.x;
    if (i < N_NODES) g_deg[i] = 0;
}

// ---------------- kernel: GEMM1  h1 = x @ W1  (M=10000, N=512, K=512, fp32) ----
#define BM 128
#define BN 64
#define BK 16
#define TM 8
#define TN 4
__global__ __launch_bounds__(256) void k_gemm1(const float* __restrict__ A,
                                               const float* __restrict__ B) {
    __shared__ float As[BK][BM + 4];
    __shared__ float Bs[BK][BN];
    const int bm = blockIdx.x * BM;
    const int bn = blockIdx.y * BN;
    const int tid = threadIdx.x;
    const int tx = tid & 15;      // 16 cols of TN=4  -> 64
    const int ty = tid >> 4;      // 16 rows of TM=8  -> 128

    float acc[TM][TN];
#pragma unroll
    for (int i = 0; i < TM; i++)
#pragma unroll
        for (int j = 0; j < TN; j++) acc[i][j] = 0.f;

    for (int k0 = 0; k0 < IN_CH; k0 += BK) {
        // load A tile (128 x 16) transposed into As[k][m]; 512 float4 slots, 2/thread
#pragma unroll
        for (int i = 0; i < 2; i++) {
            int slot = tid + i * 256;
            int row = slot >> 2;
            int kq = (slot & 3) * 4;
            float4 v = make_float4(0.f, 0.f, 0.f, 0.f);
            int gm = bm + row;
            if (gm < N_NODES) v = *(const float4*)(A + (size_t)gm * IN_CH + k0 + kq);
            As[kq + 0][row] = v.x;
            As[kq + 1][row] = v.y;
            As[kq + 2][row] = v.z;
            As[kq + 3][row] = v.w;
        }
        // load B tile (16 x 64): 256 float4 slots, 1/thread
        {
            int row = tid >> 4;
            int col = (tid & 15) * 4;
            float4 v = *(const float4*)(B + (size_t)(k0 + row) * D1 + bn + col);
            *(float4*)&Bs[row][col] = v;
        }
        __syncthreads();

#pragma unroll
        for (int kk = 0; kk < BK; kk++) {
            float4 a0 = *(const float4*)&As[kk][ty * TM];
            float4 a1 = *(const float4*)&As[kk][ty * TM + 4];
            float4 bv = *(const float4*)&Bs[kk][tx * TN];
            float av[TM] = {a0.x, a0.y, a0.z, a0.w, a1.x, a1.y, a1.z, a1.w};
            float bw[TN] = {bv.x, bv.y, bv.z, bv.w};
#pragma unroll
            for (int i = 0; i < TM; i++)
#pragma unroll
                for (int j = 0; j < TN; j++) acc[i][j] = fmaf(av[i], bw[j], acc[i][j]);
        }
        __syncthreads();
    }

#pragma unroll
    for (int i = 0; i < TM; i++) {
        int gm = bm + ty * TM + i;
        if (gm < N_NODES) {
            float4 v = make_float4(acc[i][0], acc[i][1], acc[i][2], acc[i][3]);
            *(float4*)(g_h1 + (size_t)gm * D1 + bn + tx * TN) = v;
        }
    }
}

// ---------------- kernel: per-node attention scalars a_src1/a_dst1 ----------------
__global__ void k_att1(const float* __restrict__ as1, const float* __restrict__ ad1) {
    int n = blockIdx.x;
    int h = threadIdx.x >> 5;
    int lane = threadIdx.x & 31;
    float4 hv = ((const float4*)g_h1)[(size_t)n * 128 + h * 32 + lane];
    float4 sa = ((const float4*)as1)[h * 32 + lane];
    float4 da = ((const float4*)ad1)[h * 32 + lane];
    float s = hv.x * sa.x + hv.y * sa.y + hv.z * sa.z + hv.w * sa.w;
    float d = hv.x * da.x + hv.y * da.y + hv.z * da.z + hv.w * da.w;
#pragma unroll
    for (int o = 16; o > 0; o >>= 1) {
        s += __shfl_xor_sync(0xffffffffu, s, o);
        d += __shfl_xor_sync(0xffffffffu, d, o);
    }
    if (lane == 0) {
        g_asrc1[n * HEADS + h] = s;
        g_adst1[n * HEADS + h] = d;
    }
}

// ---------------- CSR build: histogram / scan / scatter ----------------
__global__ void k_hist(const int* __restrict__ ei) {
    int e = blockIdx.x * blockDim.x + threadIdx.x;
    if (e >= E2) return;
    int dst = (e < N_EDGES) ? ei[N_EDGES + e] : (e - N_EDGES);
    atomicAdd(&g_deg[dst], 1);
}

__global__ void k_scan() {
    __shared__ int part[1024];
    const int tid = threadIdx.x;
    const int CH = (N_NODES + 1023) / 1024;  // 10
    int base = tid * CH;
    int s = 0;
    for (int i = 0; i < CH; i++) {
        int idx = base + i;
        if (idx < N_NODES) s += g_deg[idx];
    }
    part[tid] = s;
    __syncthreads();
    for (int off = 1; off < 1024; off <<= 1) {
        int v = (tid >= off) ? part[tid - off] : 0;
        __syncthreads();
        part[tid] += v;
        __syncthreads();
    }
    int run = (tid == 0) ? 0 : part[tid - 1];
    for (int i = 0; i < CH; i++) {
        int idx = base + i;
        if (idx < N_NODES) {
            g_row[idx] = run;
            g_cur[idx] = run;
            run += g_deg[idx];
        }
    }
    if (tid == 1023) g_row[N_NODES] = part[1023];
}

__global__ void k_scatter(const int* __restrict__ ei) {
    int e = blockIdx.x * blockDim.x + threadIdx.x;
    if (e >= E2) return;
    int src, dst;
    if (e < N_EDGES) {
        src = ei[e];
        dst = ei[N_EDGES + e];
    } else {
        src = dst = e - N_EDGES;
    }
    int p = atomicAdd(&g_cur[dst], 1);
    g_csr[p] = src;
}

// ---------------- kernel: layer-1 softmax-aggregate + bias + ELU ----------------
// one 128-thread CTA per dst node; thread t owns channels [4t, 4t+4); head = t/32.
__global__ __launch_bounds__(128) void k_agg1(const float* __restrict__ b1) {
    const int n = blockIdx.x;
    const int tid = threadIdx.x;
    __shared__ float4 red[128];
    __shared__ float s_ad[4];
    if (tid < 4) s_ad[tid] = g_adst1[n * HEADS + tid];
    __syncthreads();
    const int beg = g_row[n];
    const int end = g_row[n + 1];
    const float a0 = s_ad[0], a1 = s_ad[1], a2 = s_ad[2], a3 = s_ad[3];

    // pass A: per-head max over incoming edges
    float4 mx = make_float4(-INFINITY, -INFINITY, -INFINITY, -INFINITY);
    for (int k = beg + tid; k < end; k += 128) {
        int s = g_csr[k];
        const float* as = &g_asrc1[s * HEADS];
        mx.x = fmaxf(mx.x, lrelu(as[0] + a0));
        mx.y = fmaxf(mx.y, lrelu(as[1] + a1));
        mx.z = fmaxf(mx.z, lrelu(as[2] + a2));
        mx.w = fmaxf(mx.w, lrelu(as[3] + a3));
    }
    red[tid] = mx;
    __syncthreads();
#pragma unroll
    for (int off = 64; off > 0; off >>= 1) {
        if (tid < off) {
            float4 u = red[tid], v = red[tid + off];
            u.x = fmaxf(u.x, v.x);
            u.y = fmaxf(u.y, v.y);
            u.z = fmaxf(u.z, v.z);
            u.w = fmaxf(u.w, v.w);
            red[tid] = u;
        }
        __syncthreads();
    }
    const float4 M4 = red[0];

    const int h = tid >> 5;
    const float mh = (h == 0) ? M4.x : (h == 1) ? M4.y : (h == 2) ? M4.z : M4.w;
    const float ah = (h == 0) ? a0 : (h == 1) ? a1 : (h == 2) ? a2 : a3;

    // pass B: every thread walks all edges; unnormalized accumulate + own denominator
    const float4* h1v = (const float4*)g_h1;
    float4 acc = make_float4(0.f, 0.f, 0.f, 0.f);
    float den = 0.f;
    for (int k = beg; k < end; k++) {
        int s = g_csr[k];  // broadcast load
        float e = lrelu(g_asrc1[s * HEADS + h] + ah);
        float ex = expf(e - mh);
        den += ex;
        float4 hv = h1v[(size_t)s * 128 + tid];
        acc.x = fmaf(ex, hv.x, acc.x);
        acc.y = fmaf(ex, hv.y, acc.y);
        acc.z = fmaf(ex, hv.z, acc.z);
        acc.w = fmaf(ex, hv.w, acc.w);
    }
    const float inv = 1.f / (den + 1e-16f);
    float4 bb = ((const float4*)b1)[tid];
    float o0 = acc.x * inv + bb.x;
    float o1 = acc.y * inv + bb.y;
    float o2 = acc.z * inv + bb.z;
    float o3 = acc.w * inv + bb.w;
    // ELU (alpha=1)
    o0 = o0 > 0.f ? o0 : expm1f(o0);
    o1 = o1 > 0.f ? o1 : expm1f(o1);
    o2 = o2 > 0.f ? o2 : expm1f(o2);
    o3 = o3 > 0.f ? o3 : expm1f(o3);
    ((float4*)g_act1)[(size_t)n * 128 + tid] = make_float4(o0, o1, o2, o3);
}

// ---------------- kernel: layer-2 GEMV (512->2) + attention scalars ----------------
__global__ __launch_bounds__(128) void k_l2(const float* __restrict__ W2,
                                            const float* __restrict__ as2,
                                            const float* __restrict__ ad2) {
    const int n = blockIdx.x;
    const int tid = threadIdx.x;
    __shared__ float2 red[128];
    float4 a = ((const float4*)g_act1)[(size_t)n * 128 + tid];
    float4 w01 = ((const float4*)W2)[tid * 2];      // W2[4t..4t+1][0..1]
    float4 w23 = ((const float4*)W2)[tid * 2 + 1];  // W2[4t+2..4t+3][0..1]
    float s0 = a.x * w01.x + a.y * w01.z + a.z * w23.x + a.w * w23.z;
    float s1 = a.x * w01.y + a.y * w01.w + a.z * w23.y + a.w * w23.w;
    red[tid] = make_float2(s0, s1);
    __syncthreads();
#pragma unroll
    for (int off = 64; off > 0; off >>= 1) {
        if (tid < off) {
            red[tid].x += red[tid + off].x;
            red[tid].y += red[tid + off].y;
        }
        __syncthreads();
    }
    if (tid == 0) {
        float h0 = red[0].x, h1 = red[0].y;
        g_h2[n * 2] = h0;
        g_h2[n * 2 + 1] = h1;
        g_asrc2[n] = h0 * as2[0] + h1 * as2[1];
        g_adst2[n] = h0 * ad2[0] + h1 * ad2[1];
    }
}

// ---------------- kernel: layer-2 aggregate (one warp per node) ----------------
__global__ __launch_bounds__(128) void k_agg2(const float* __restrict__ b2,
                                              float* __restrict__ out) {
    const int warp = threadIdx.x >> 5;
    const int lane = threadIdx.x & 31;
    const int n = blockIdx.x * 4 + warp;
    if (n >= N_NODES) return;
    const int beg = g_row[n];
    const int end = g_row[n + 1];
    const float ad = g_adst2[n];

    float mx = -INFINITY;
    for (int k = beg + lane; k < end; k += 32)
        mx = fmaxf(mx, lrelu(g_asrc2[g_csr[k]] + ad));
#pragma unroll
    for (int o = 16; o > 0; o >>= 1) mx = fmaxf(mx, __shfl_xor_sync(0xffffffffu, mx, o));

    float den = 0.f, c0 = 0.f, c1 = 0.f;
    for (int k = beg + lane; k < end; k += 32) {
        int s = g_csr[k];
        float e = lrelu(g_asrc2[s] + ad);
        float ex = expf(e - mx);
        den += ex;
        float2 hv = ((const float2*)g_h2)[s];
        c0 = fmaf(ex, hv.x, c0);
        c1 = fmaf(ex, hv.y, c1);
    }
#pragma unroll
    for (int o = 16; o > 0; o >>= 1) {
        den += __shfl_xor_sync(0xffffffffu, den, o);
        c0 += __shfl_xor_sync(0xffffffffu, c0, o);
        c1 += __shfl_xor_sync(0xffffffffu, c1, o);
    }
    if (lane == 0) {
        float inv = 1.f / (den + 1e-16f);
        out[n * 2] = c0 * inv + b2[0];
        out[n * 2 + 1] = c1 * inv + b2[1];
    }
}

// ---------------- launch ----------------
extern "C" void kernel_launch(void* const* d_in, const int* in_sizes, int n_in,
                              void* d_out, int out_size) {
    const float* x   = (const float*)d_in[0];
    const int*   ei  = (const int*)d_in[1];
    const float* W1  = (const float*)d_in[2];
    const float* as1 = (const float*)d_in[3];
    const float* ad1 = (const float*)d_in[4];
    const float* b1  = (const float*)d_in[5];
    const float* W2  = (const float*)d_in[6];
    const float* as2 = (const float*)d_in[7];
    const float* ad2 = (const float*)d_in[8];
    const float* b2  = (const float*)d_in[9];
    float* out = (float*)d_out;

    k_zero<<<(N_NODES + 255) / 256, 256>>>();
    k_gemm1<<<dim3((N_NODES + BM - 1) / BM, D1 / BN), 256>>>(x, W1);
    k_att1<<<N_NODES, 128>>>(as1, ad1);
    k_hist<<<(E2 + 255) / 256, 256>>>(ei);
    k_scan<<<1, 1024>>>();
    k_scatter<<<(E2 + 255) / 256, 256>>>(ei);
    k_agg1<<<N_NODES, 128>>>(b1);
    k_l2<<<N_NODES, 128>>>(W2, as2, ad2);
    k_agg2<<<(N_NODES + 3) / 4, 128>>>(b2, out);
}